// round 9
// baseline (speedup 1.0000x reference)
#include <cuda_runtime.h>
#include <cuda_bf16.h>
#include <math.h>
#include <cstdint>

#define BB 16
#define LL 512
#define HIDN 768
#define HH 12
#define DD 64
#define NSTRUCT 5
#define BH (BB*HH)   // 192

typedef unsigned long long ull;

// ---- packed f32x2 helpers ----
__device__ __forceinline__ void fma2(ull &d, ull a, ull b) {
    asm("fma.rn.f32x2 %0, %1, %2, %0;" : "+l"(d) : "l"(a), "l"(b));
}
__device__ __forceinline__ void mul2(ull &d, ull s) {
    asm("mul.rn.f32x2 %0, %0, %1;" : "+l"(d) : "l"(s));
}
__device__ __forceinline__ ull pack2(float lo, float hi) {
    ull r; asm("mov.b64 %0, {%1, %2};" : "=l"(r) : "f"(lo), "f"(hi)); return r;
}
__device__ __forceinline__ float2 unpack2(ull v) {
    float2 r; asm("mov.b64 {%0, %1}, %2;" : "=f"(r.x), "=f"(r.y) : "l"(v)); return r;
}

// ---- warp MMA helpers ----
__device__ __forceinline__ uint32_t smem_u32(const void* p) {
    uint32_t a;
    asm("{ .reg .u64 t; cvta.to.shared.u64 t, %1; cvt.u32.u64 %0, t; }" : "=r"(a) : "l"(p));
    return a;
}
#define LDSM4(r, addr) \
    asm volatile("ldmatrix.sync.aligned.m8n8.x4.shared.b16 {%0,%1,%2,%3}, [%4];" \
        : "=r"((r)[0]), "=r"((r)[1]), "=r"((r)[2]), "=r"((r)[3]) : "r"(addr))

__device__ __forceinline__ void mma_bf16(float* c, const uint32_t* a, const uint32_t* b) {
    asm volatile("mma.sync.aligned.m16n8k16.row.col.f32.bf16.bf16.f32 "
        "{%0,%1,%2,%3}, {%4,%5,%6,%7}, {%8,%9}, {%0,%1,%2,%3};"
        : "+f"(c[0]), "+f"(c[1]), "+f"(c[2]), "+f"(c[3])
        : "r"(a[0]), "r"(a[1]), "r"(a[2]), "r"(a[3]), "r"(b[0]), "r"(b[1]));
}
#define CP_ASYNC16(sa, gp) \
    asm volatile("cp.async.cg.shared.global [%0], [%1], 16;" :: "r"(sa), "l"(gp))
#define CP_COMMIT() asm volatile("cp.async.commit_group;" ::: "memory")
#define CP_WAIT1()  asm volatile("cp.async.wait_group 1;" ::: "memory")
#define CP_WAIT0()  asm volatile("cp.async.wait_group 0;" ::: "memory")

// ---------------- scratch ----------------
__device__ float    g_Q [BH * LL * DD];            // fp32 Q (qb_kernel input)
__device__ float    g_V [BH * LL * DD];            // fp32 V (PV path)
__device__ unsigned g_MB[NSTRUCT * BB * LL * (LL/32)];
__device__ __nv_bfloat16 g_hsH[BB*LL*HIDN], g_hsL[BB*LL*HIDN];
__device__ __nv_bfloat16 g_WH [3*HIDN*HIDN], g_WL [3*HIDN*HIDN];
// pre-split bf16 operands for attention MMA
__device__ __nv_bfloat16 g_QH [BH * LL * DD], g_QL [BH * LL * DD];
__device__ __nv_bfloat16 g_KH [BH * LL * DD], g_KL [BH * LL * DD];
__device__ __nv_bfloat16 g_QBH[NSTRUCT * BH * LL * DD], g_QBL[NSTRUCT * BH * LL * DD];

// =============================================================================
// Kernel 0a: pack structure mask to bits.
// =============================================================================
__global__ void __launch_bounds__(256) pack_mask(const float* __restrict__ smask)
{
    size_t e = (size_t)blockIdx.x * 256 + threadIdx.x;
    float v = smask[e];
    unsigned bal = __ballot_sync(0xffffffffu, v != 0.f);
    if ((threadIdx.x & 31) == 0) g_MB[e >> 5] = bal;
}

// =============================================================================
// Kernel 0b/0c: split fp32 -> bf16 hi/lo
// =============================================================================
__device__ __forceinline__ void split2(float a, float b, __nv_bfloat162* H, __nv_bfloat162* L) {
    __nv_bfloat16 ah = __float2bfloat16_rn(a), bh = __float2bfloat16_rn(b);
    __nv_bfloat16 al = __float2bfloat16_rn(a - __bfloat162float(ah));
    __nv_bfloat16 bl = __float2bfloat16_rn(b - __bfloat162float(bh));
    *H = __nv_bfloat162(ah, bh);
    *L = __nv_bfloat162(al, bl);
}
__global__ void __launch_bounds__(256) cvt_hs(const float* __restrict__ hs)
{
    size_t i = (size_t)blockIdx.x * 256 + threadIdx.x;
    float4 v = ((const float4*)hs)[i];
    __nv_bfloat162 h0, l0, h1, l1;
    split2(v.x, v.y, &h0, &l0);
    split2(v.z, v.w, &h1, &l1);
    ((__nv_bfloat162*)g_hsH)[2*i]   = h0;
    ((__nv_bfloat162*)g_hsH)[2*i+1] = h1;
    ((__nv_bfloat162*)g_hsL)[2*i]   = l0;
    ((__nv_bfloat162*)g_hsL)[2*i+1] = l1;
}
__global__ void __launch_bounds__(256) cvt_w(const float* __restrict__ Wq,
                                             const float* __restrict__ Wk,
                                             const float* __restrict__ Wv)
{
    size_t i = (size_t)blockIdx.x * 256 + threadIdx.x;
    const size_t per = (size_t)HIDN*HIDN/4;
    const float* src = (i < per) ? Wq : (i < 2*per) ? Wk : Wv;
    size_t loc = i % per;
    float4 v = ((const float4*)src)[loc];
    __nv_bfloat162 h0, l0, h1, l1;
    split2(v.x, v.y, &h0, &l0);
    split2(v.z, v.w, &h1, &l1);
    ((__nv_bfloat162*)g_WH)[2*i]   = h0;
    ((__nv_bfloat162*)g_WH)[2*i+1] = h1;
    ((__nv_bfloat162*)g_WL)[2*i]   = l0;
    ((__nv_bfloat162*)g_WL)[2*i+1] = l1;
}

// =============================================================================
// Kernel 1: QKV projection on mma.sync bf16 (split bf16x3).
// Epilogue writes: z=0 -> fp32 g_Q + split g_QH/g_QL
//                  z=1 -> split g_KH/g_KL only
//                  z=2 -> fp32 g_V only
// =============================================================================
#define QT_ROWB 80
#define QT_TILE (128 * QT_ROWB)
#define QT_STAGE (4 * QT_TILE)
#define QT_SMEM (2 * QT_STAGE)
#define NCHUNK (HIDN / 32)

__global__ void __launch_bounds__(256) qkv_mma_kernel(
    const float* __restrict__ bq, const float* __restrict__ bk, const float* __restrict__ bv)
{
    extern __shared__ __align__(16) char smem[];
    const uint32_t sb = smem_u32(smem);

    const int t = threadIdx.x, wid = t >> 5, lane = t & 31;
    const int m0 = blockIdx.x * 128;
    const int n0 = blockIdx.y * 128;
    const int z  = blockIdx.z;
    const float* bias = (z == 0) ? bq : (z == 1) ? bk : bv;
    const __nv_bfloat16* BHg = g_WH + (size_t)z * HIDN * HIDN;
    const __nv_bfloat16* BLg = g_WL + (size_t)z * HIDN * HIDN;

    const int wm = (wid & 1) * 64;
    const int wn = (wid >> 1) * 32;

    float C[4][4][4];
#pragma unroll
    for (int i = 0; i < 4; i++)
#pragma unroll
        for (int j = 0; j < 4; j++)
#pragma unroll
            for (int k = 0; k < 4; k++) C[i][j][k] = 0.f;

    const uint32_t a_off = (uint32_t)((wm + (lane & 7) + ((lane >> 3) & 1) * 8) * QT_ROWB
                                      + ((lane >> 4) * 8) * 2);
    const uint32_t b_off = (uint32_t)((wn + (lane & 7) + (lane >> 4) * 8) * QT_ROWB
                                      + (((lane >> 3) & 1) * 8) * 2);

    const int lr0 = t >> 2, lu0 = t & 3;
    const int lr1 = (t + 256) >> 2, lu1 = t & 3;

    {
        const int k0 = 0;
        uint32_t s0 = sb;
#pragma unroll
        for (int p = 0; p < 2; ++p) {
            int r = p ? lr1 : lr0, u = p ? lu1 : lu0;
            uint32_t so = (uint32_t)(r * QT_ROWB + u * 16);
            size_t ga = (size_t)(m0 + r) * HIDN + k0 + u * 8;
            size_t gb = (size_t)(n0 + r) * HIDN + k0 + u * 8;
            CP_ASYNC16(s0 + 0*QT_TILE + so, g_hsH + ga);
            CP_ASYNC16(s0 + 1*QT_TILE + so, g_hsL + ga);
            CP_ASYNC16(s0 + 2*QT_TILE + so, BHg + gb);
            CP_ASYNC16(s0 + 3*QT_TILE + so, BLg + gb);
        }
        CP_COMMIT();
    }

    for (int ch = 0; ch < NCHUNK; ++ch) {
        if (ch + 1 < NCHUNK) {
            const int k0 = (ch + 1) * 32;
            uint32_t s1 = sb + ((ch + 1) & 1) * QT_STAGE;
#pragma unroll
            for (int p = 0; p < 2; ++p) {
                int r = p ? lr1 : lr0, u = p ? lu1 : lu0;
                uint32_t so = (uint32_t)(r * QT_ROWB + u * 16);
                size_t ga = (size_t)(m0 + r) * HIDN + k0 + u * 8;
                size_t gb = (size_t)(n0 + r) * HIDN + k0 + u * 8;
                CP_ASYNC16(s1 + 0*QT_TILE + so, g_hsH + ga);
                CP_ASYNC16(s1 + 1*QT_TILE + so, g_hsL + ga);
                CP_ASYNC16(s1 + 2*QT_TILE + so, BHg + gb);
                CP_ASYNC16(s1 + 3*QT_TILE + so, BLg + gb);
            }
            CP_COMMIT();
            CP_WAIT1();
        } else {
            CP_WAIT0();
        }
        __syncthreads();

        const uint32_t st = sb + (ch & 1) * QT_STAGE;
        const uint32_t aH = st + 0*QT_TILE + a_off;
        const uint32_t aL = st + 1*QT_TILE + a_off;
        const uint32_t bHb = st + 2*QT_TILE + b_off;
        const uint32_t bLb = st + 3*QT_TILE + b_off;

#pragma unroll
        for (int ks = 0; ks < 2; ++ks) {
            const uint32_t ko = ks * 32;
            uint32_t ah[4][4], al[4][4], bh[4][2], bl[4][2];
#pragma unroll
            for (int mt = 0; mt < 4; ++mt) {
                LDSM4(ah[mt], aH + mt * 16 * QT_ROWB + ko);
                LDSM4(al[mt], aL + mt * 16 * QT_ROWB + ko);
            }
#pragma unroll
            for (int p = 0; p < 2; ++p) {
                uint32_t r4[4];
                LDSM4(r4, bHb + p * 16 * QT_ROWB + ko);
                bh[2*p][0] = r4[0]; bh[2*p][1] = r4[1];
                bh[2*p+1][0] = r4[2]; bh[2*p+1][1] = r4[3];
                LDSM4(r4, bLb + p * 16 * QT_ROWB + ko);
                bl[2*p][0] = r4[0]; bl[2*p][1] = r4[1];
                bl[2*p+1][0] = r4[2]; bl[2*p+1][1] = r4[3];
            }
#pragma unroll
            for (int mt = 0; mt < 4; ++mt)
#pragma unroll
                for (int nt = 0; nt < 4; ++nt) {
                    mma_bf16(C[mt][nt], ah[mt], bh[nt]);
                    mma_bf16(C[mt][nt], ah[mt], bl[nt]);
                    mma_bf16(C[mt][nt], al[mt], bh[nt]);
                }
        }
        __syncthreads();
    }

    // ---- epilogue ----
#pragma unroll
    for (int mt = 0; mt < 4; ++mt) {
        const int m = m0 + wm + mt * 16 + (lane >> 2);
        const int b = m >> 9, l = m & 511;
#pragma unroll
        for (int nt = 0; nt < 4; ++nt) {
            const int n = n0 + wn + nt * 8 + (lane & 3) * 2;
            const int hd = n >> 6, d = n & 63;
            const float b0 = __ldg(bias + n), b1 = __ldg(bias + n + 1);
            const size_t o1 = ((size_t)(b * HH + hd) * LL + l) * DD + d;
            const size_t o2 = ((size_t)(b * HH + hd) * LL + (l + 8)) * DD + d;
            float v00 = C[mt][nt][0] + b0, v01 = C[mt][nt][1] + b1;
            float v10 = C[mt][nt][2] + b0, v11 = C[mt][nt][3] + b1;
            if (z == 0) {
                *(float2*)(g_Q + o1) = make_float2(v00, v01);
                *(float2*)(g_Q + o2) = make_float2(v10, v11);
                __nv_bfloat162 hh, llo;
                split2(v00, v01, &hh, &llo);
                *(__nv_bfloat162*)(g_QH + o1) = hh;
                *(__nv_bfloat162*)(g_QL + o1) = llo;
                split2(v10, v11, &hh, &llo);
                *(__nv_bfloat162*)(g_QH + o2) = hh;
                *(__nv_bfloat162*)(g_QL + o2) = llo;
            } else if (z == 1) {
                __nv_bfloat162 hh, llo;
                split2(v00, v01, &hh, &llo);
                *(__nv_bfloat162*)(g_KH + o1) = hh;
                *(__nv_bfloat162*)(g_KL + o1) = llo;
                split2(v10, v11, &hh, &llo);
                *(__nv_bfloat162*)(g_KH + o2) = hh;
                *(__nv_bfloat162*)(g_KL + o2) = llo;
            } else {
                *(float2*)(g_V + o1) = make_float2(v00, v01);
                *(float2*)(g_V + o2) = make_float2(v10, v11);
            }
        }
    }
}

// =============================================================================
// Kernel 2: QB = Q @ bili (SIMT), writes pre-split bf16.
// =============================================================================
__global__ void __launch_bounds__(256) qb_kernel(const float* __restrict__ bili)
{
    const int mt = blockIdx.x, h = blockIdx.y, s = blockIdx.z;
    const int m0 = mt * 64;
    const int b = m0 >> 9, l0 = m0 & 511;
    const float* qbase = g_Q + (size_t)(b*HH + h) * LL * DD;
    const float* Bm    = bili + (size_t)(s*HH + h) * DD * DD;
    const size_t dstoff = (size_t)((s*BB + b)*HH + h) * LL * DD;

    __shared__ __align__(16) float As[16 * 68];
    __shared__ __align__(16) float Bs[16 * 68];

    const int t = threadIdx.x;
    const int mload = t >> 2, kv = t & 3;
    const int kl = t >> 4, nv = t & 15;
    const int ty = t >> 4, tx = t & 15;

    float c[4][4];
#pragma unroll
    for (int i = 0; i < 4; i++)
#pragma unroll
        for (int j = 0; j < 4; j++) c[i][j] = 0.f;

    for (int k0 = 0; k0 < DD; k0 += 16) {
        float4 a4 = *(const float4*)(qbase + (size_t)(l0 + mload) * DD + k0 + kv * 4);
        As[(kv*4+0)*68 + mload] = a4.x;
        As[(kv*4+1)*68 + mload] = a4.y;
        As[(kv*4+2)*68 + mload] = a4.z;
        As[(kv*4+3)*68 + mload] = a4.w;
        float4 b4 = *(const float4*)(Bm + (size_t)(k0 + kl) * DD + nv * 4);
        Bs[kl*68 + nv*4+0] = b4.x;
        Bs[kl*68 + nv*4+1] = b4.y;
        Bs[kl*68 + nv*4+2] = b4.z;
        Bs[kl*68 + nv*4+3] = b4.w;
        __syncthreads();
#pragma unroll
        for (int k = 0; k < 16; k++) {
            float4 av4 = *(const float4*)&As[k*68 + ty*4];
            float4 bv4 = *(const float4*)&Bs[k*68 + tx*4];
            float a[4] = {av4.x, av4.y, av4.z, av4.w};
            float bb[4] = {bv4.x, bv4.y, bv4.z, bv4.w};
#pragma unroll
            for (int i = 0; i < 4; i++)
#pragma unroll
                for (int j = 0; j < 4; j++) c[i][j] += a[i] * bb[j];
        }
        __syncthreads();
    }

#pragma unroll
    for (int i = 0; i < 4; i++) {
        const size_t ro = dstoff + (size_t)(l0 + ty*4 + i) * DD + tx*4;
        __nv_bfloat162 hh, llo;
        split2(c[i][0], c[i][1], &hh, &llo);
        *(__nv_bfloat162*)(g_QBH + ro)     = hh;
        *(__nv_bfloat162*)(g_QBL + ro)     = llo;
        split2(c[i][2], c[i][3], &hh, &llo);
        *(__nv_bfloat162*)(g_QBH + ro + 2) = hh;
        *(__nv_bfloat162*)(g_QBL + ro + 2) = llo;
    }
}

// =============================================================================
// Kernel 3: fused attention with mma.sync scores; all bf16 operands pre-split.
// =============================================================================
#define A_QH 0
#define A_QL (A_QH + 6*64*144)          // 55296
#define A_KH (A_QL + 6*64*144)          // 110592
#define A_KL (A_KH + 128*144)           // 129024
#define A_VT (A_KL + 128*144)           // 147456
#define A_SC (A_VT + 64*130*4)          // 180736
#define A_TOT (A_SC + 64*132*4)         // 214528

__device__ __forceinline__ float warp_max(float v) {
#pragma unroll
    for (int off = 16; off > 0; off >>= 1)
        v = fmaxf(v, __shfl_xor_sync(0xffffffffu, v, off));
    return v;
}
__device__ __forceinline__ float warp_sum(float v) {
#pragma unroll
    for (int off = 16; off > 0; off >>= 1)
        v += __shfl_xor_sync(0xffffffffu, v, off);
    return v;
}

__global__ void __launch_bounds__(256) attn_kernel(
    const float* __restrict__ amask,
    const float* __restrict__ absb,
    float* __restrict__ out)
{
    extern __shared__ __align__(16) char smem[];
    const uint32_t sb = smem_u32(smem);
    float* vt = (float*)(smem + A_VT);
    float* sc = (float*)(smem + A_SC);

    const int t    = threadIdx.x;
    const int w    = t >> 5;
    const int lane = t & 31;
    const int bh   = blockIdx.y;
    const int b = bh / HH, h = bh % HH;
    const int i0 = blockIdx.x * 64;

    const __nv_bfloat16* QHb = g_QH + (size_t)bh * LL * DD;
    const __nv_bfloat16* QLb = g_QL + (size_t)bh * LL * DD;
    const __nv_bfloat16* KHb = g_KH + (size_t)bh * LL * DD;
    const __nv_bfloat16* KLb = g_KL + (size_t)bh * LL * DD;
    const float* Vb = g_V + (size_t)bh * LL * DD;

    // ---- load q + 5 qb components (pre-split bf16, straight copies) ----
    for (int f = t; f < 6 * 64 * 8; f += 256) {
        int c = f >> 9;             // component (64 rows * 8 u4 = 512)
        int r = (f >> 3) & 63;
        int u = f & 7;
        const size_t go = (c == 0)
            ? (size_t)(QHb - g_QH) + (size_t)(i0 + r) * DD + u * 8
            : (size_t)((c - 1) * BB + b) * HH * LL * DD + (size_t)h * LL * DD
              + (size_t)(i0 + r) * DD + u * 8;
        const __nv_bfloat16* sH = (c == 0) ? (g_QH + go) : (g_QBH + go);
        const __nv_bfloat16* sL = (c == 0) ? (g_QL + go) : (g_QBL + go);
        char* p = smem + (c * 64 + r) * 144 + u * 16;
        *(uint4*)(p + A_QH) = *(const uint4*)sH;
        *(uint4*)(p + A_QL) = *(const uint4*)sL;
    }

    float ab[NSTRUCT];
#pragma unroll
    for (int s = 0; s < NSTRUCT; ++s) ab[s] = __ldg(absb + s*HH + h);

    float mrow[8], lrow[8];
    ull ctx2[8][2];
#pragma unroll
    for (int i = 0; i < 8; ++i) {
        mrow[i] = -1e30f; lrow[i] = 0.f;
        ctx2[i][0] = 0ULL; ctx2[i][1] = 0ULL;
    }

    const int row0 = w * 8;
    const int wm = (w & 1) * 32;
    const int wn = (w >> 1) * 32;

    const uint32_t a_base = sb + A_QH
        + (uint32_t)((wm + (lane & 7) + ((lane >> 3) & 1) * 8) * 144 + (lane >> 4) * 16);
    const uint32_t b_base = sb + A_KH
        + (uint32_t)((wn + (lane & 7) + (lane >> 4) * 8) * 144 + ((lane >> 3) & 1) * 16);
    const uint32_t QLOFF = A_QL - A_QH;
    const uint32_t KLOFF = A_KL - A_KH;

    for (int jt = 0; jt < 4; ++jt) {
        const int j0 = jt * 128;
        __syncthreads();
        // ---- load K tile (pre-split bf16) ----
        for (int f = t; f < 128 * 8; f += 256) {
            int j = f >> 3, u = f & 7;
            const size_t go = (size_t)(j0 + j) * DD + u * 8;
            char* p = smem + j * 144 + u * 16;
            *(uint4*)(p + A_KH) = *(const uint4*)(KHb + go);
            *(uint4*)(p + A_KL) = *(const uint4*)(KLb + go);
        }
        // ---- load V tile (fp32, transposed [d][j]) ----
        for (int f = t; f < 2048; f += 256) {
            int j = f >> 4, dv = f & 15;
            float4 v4 = *(const float4*)(Vb + (size_t)(j0 + j) * DD + dv * 4);
            vt[(dv*4+0)*130 + j] = v4.x;
            vt[(dv*4+1)*130 + j] = v4.y;
            vt[(dv*4+2)*130 + j] = v4.z;
            vt[(dv*4+3)*130 + j] = v4.w;
        }
        __syncthreads();

        // ---- MMA: S fragment ----
        float S[2][4][4];
#pragma unroll
        for (int i = 0; i < 2; ++i)
#pragma unroll
            for (int j = 0; j < 4; ++j)
#pragma unroll
                for (int k = 0; k < 4; ++k) S[i][j][k] = 0.f;

        const int widx = jt * 4 + (wn >> 5);

        for (int c = 0; c < 6; ++c) {
            float Sc[2][4][4];
            float (*acc)[4][4] = (c == 0) ? S : Sc;
            if (c != 0) {
#pragma unroll
                for (int i = 0; i < 2; ++i)
#pragma unroll
                    for (int j = 0; j < 4; ++j)
#pragma unroll
                        for (int k = 0; k < 4; ++k) Sc[i][j][k] = 0.f;
            }
            const uint32_t aH = a_base + (uint32_t)(c * 64 * 144);
#pragma unroll
            for (int ks = 0; ks < 4; ++ks) {
                const uint32_t ko = ks * 32;
                uint32_t ah[2][4], al[2][4], bhf[4][2], blf[4][2];
#pragma unroll
                for (int mt = 0; mt < 2; ++mt) {
                    LDSM4(ah[mt], aH + mt * 16 * 144 + ko);
                    LDSM4(al[mt], aH + QLOFF + mt * 16 * 144 + ko);
                }
#pragma unroll
                for (int p = 0; p < 2; ++p) {
                    uint32_t r4[4];
                    LDSM4(r4, b_base + p * 16 * 144 + ko);
                    bhf[2*p][0] = r4[0]; bhf[2*p][1] = r4[1];
                    bhf[2*p+1][0] = r4[2]; bhf[2*p+1][1] = r4[3];
                    LDSM4(r4, b_base + KLOFF + p * 16 * 144 + ko);
                    blf[2*p][0] = r4[0]; blf[2*p][1] = r4[1];
                    blf[2*p+1][0] = r4[2]; blf[2*p+1][1] = r4[3];
                }
#pragma unroll
                for (int mt = 0; mt < 2; ++mt)
#pragma unroll
                    for (int nt = 0; nt < 4; ++nt) {
                        mma_bf16(acc[mt][nt], ah[mt], bhf[nt]);
                        mma_bf16(acc[mt][nt], ah[mt], blf[nt]);
                        mma_bf16(acc[mt][nt], al[mt], bhf[nt]);
                    }
            }
            if (c != 0) {
                const int s = c - 1;
                const float abs_s = ab[s];
                const size_t mrowbase = ((size_t)(s*BB + b) * LL + i0 + wm) * 16;
#pragma unroll
                for (int mt = 0; mt < 2; ++mt) {
                    const int rloc = mt * 16 + (lane >> 2);
                    unsigned mw0 = g_MB[mrowbase + (size_t)rloc * 16 + widx];
                    unsigned mw1 = g_MB[mrowbase + (size_t)(rloc + 8) * 16 + widx];
#pragma unroll
                    for (int nt = 0; nt < 4; ++nt) {
                        const int bp = nt * 8 + (lane & 3) * 2;
                        S[mt][nt][0] += (float)((mw0 >> bp) & 1u)     * (Sc[mt][nt][0] + abs_s);
                        S[mt][nt][1] += (float)((mw0 >> (bp+1)) & 1u) * (Sc[mt][nt][1] + abs_s);
                        S[mt][nt][2] += (float)((mw1 >> bp) & 1u)     * (Sc[mt][nt][2] + abs_s);
                        S[mt][nt][3] += (float)((mw1 >> (bp+1)) & 1u) * (Sc[mt][nt][3] + abs_s);
                    }
                }
            }
        }

        // ---- spill S fragments to sc ----
#pragma unroll
        for (int mt = 0; mt < 2; ++mt) {
            const int rr = wm + mt * 16 + (lane >> 2);
#pragma unroll
            for (int nt = 0; nt < 4; ++nt) {
                const int cc = wn + nt * 8 + (lane & 3) * 2;
                *(float2*)&sc[rr * 132 + cc]       = make_float2(S[mt][nt][0], S[mt][nt][1]);
                *(float2*)&sc[(rr + 8) * 132 + cc] = make_float2(S[mt][nt][2], S[mt][nt][3]);
            }
        }
        __syncthreads();

        // ---- online softmax ----
        float amv[4];
#pragma unroll
        for (int jj = 0; jj < 4; ++jj)
            amv[jj] = __ldg(amask + (size_t)b * LL + j0 + lane + 32*jj);

#pragma unroll
        for (int ii = 0; ii < 8; ++ii) {
            const int r = row0 + ii;
            float lg[4];
            float mt = -1e30f;
#pragma unroll
            for (int jj = 0; jj < 4; ++jj) {
                lg[jj] = sc[r * 132 + lane + 32*jj] * 0.125f + amv[jj];
                mt = fmaxf(mt, lg[jj]);
            }
            mt = warp_max(mt);
            float mnew = fmaxf(mrow[ii], mt);
            float corr = __expf(mrow[ii] - mnew);
            mrow[ii] = mnew;
            float psum = 0.f;
#pragma unroll
            for (int jj = 0; jj < 4; ++jj) {
                float p = __expf(lg[jj] - mnew);
                sc[r * 132 + lane + 32*jj] = p;
                psum += p;
            }
            psum = warp_sum(psum);
            lrow[ii] = lrow[ii] * corr + psum;
            ull c2 = pack2(corr, corr);
            mul2(ctx2[ii][0], c2);
            mul2(ctx2[ii][1], c2);
        }
        __syncwarp();

        // ---- PV (FFMA2) ----
        const float* vr0 = &vt[lane * 130];
        const float* vr1 = &vt[(lane + 32) * 130];
#pragma unroll 2
        for (int j2 = 0; j2 < 64; ++j2) {
            ull vv0 = *(const ull*)(vr0 + 2*j2);
            ull vv1 = *(const ull*)(vr1 + 2*j2);
#pragma unroll
            for (int ii = 0; ii < 8; ++ii) {
                ull pp = *(const ull*)&sc[(row0 + ii) * 132 + 2*j2];
                fma2(ctx2[ii][0], pp, vv0);
                fma2(ctx2[ii][1], pp, vv1);
            }
        }
    }

    // ---- finalize ----
#pragma unroll
    for (int ii = 0; ii < 8; ++ii) {
        const int ig = i0 + row0 + ii;
        float inv = 1.f / lrow[ii];
        float* op = out + (size_t)(b * LL + ig) * (HH*DD) + h * DD;
        float2 c0 = unpack2(ctx2[ii][0]);
        float2 c1 = unpack2(ctx2[ii][1]);
        op[lane]      = (c0.x + c0.y) * inv;
        op[lane + 32] = (c1.x + c1.y) * inv;
    }
}

// =============================================================================
extern "C" void kernel_launch(void* const* d_in, const int* in_sizes, int n_in,
                              void* d_out, int out_size)
{
    const float* hs   = (const float*)d_in[0];
    const float* am   = (const float*)d_in[1];
    const float* smk  = (const float*)d_in[2];
    const float* Wq   = (const float*)d_in[3];
    const float* bq   = (const float*)d_in[4];
    const float* Wk   = (const float*)d_in[5];
    const float* bk   = (const float*)d_in[6];
    const float* Wv   = (const float*)d_in[7];
    const float* bv   = (const float*)d_in[8];
    const float* bili = (const float*)d_in[9];
    const float* absb = (const float*)d_in[10];
    float* out = (float*)d_out;

    pack_mask<<<(NSTRUCT*BB*LL*LL)/256, 256>>>(smk);
    cvt_hs<<<(BB*LL*HIDN/4)/256, 256>>>(hs);
    cvt_w<<<(3*HIDN*HIDN/4)/256, 256>>>(Wq, Wk, Wv);

    cudaFuncSetAttribute(qkv_mma_kernel, cudaFuncAttributeMaxDynamicSharedMemorySize, QT_SMEM);
    qkv_mma_kernel<<<dim3(64, 6, 3), 256, QT_SMEM>>>(bq, bk, bv);

    qb_kernel<<<dim3(128, 12, 5), 256>>>(bili);

    cudaFuncSetAttribute(attn_kernel, cudaFuncAttributeMaxDynamicSharedMemorySize, A_TOT);
    attn_kernel<<<dim3(8, 192), 256, A_TOT>>>(am, absb, out);
}

// round 10
// speedup vs baseline: 1.1045x; 1.1045x over previous
#include <cuda_runtime.h>
#include <cuda_bf16.h>
#include <math.h>
#include <cstdint>

#define BB 16
#define LL 512
#define HIDN 768
#define HH 12
#define DD 64
#define NSTRUCT 5
#define BH (BB*HH)   // 192

typedef unsigned long long ull;

// ---- packed f32x2 helpers ----
__device__ __forceinline__ void fma2(ull &d, ull a, ull b) {
    asm("fma.rn.f32x2 %0, %1, %2, %0;" : "+l"(d) : "l"(a), "l"(b));
}
__device__ __forceinline__ void mul2(ull &d, ull s) {
    asm("mul.rn.f32x2 %0, %0, %1;" : "+l"(d) : "l"(s));
}
__device__ __forceinline__ ull pack2(float lo, float hi) {
    ull r; asm("mov.b64 %0, {%1, %2};" : "=l"(r) : "f"(lo), "f"(hi)); return r;
}
__device__ __forceinline__ float2 unpack2(ull v) {
    float2 r; asm("mov.b64 {%0, %1}, %2;" : "=f"(r.x), "=f"(r.y) : "l"(v)); return r;
}

// ---- warp MMA helpers ----
__device__ __forceinline__ uint32_t smem_u32(const void* p) {
    uint32_t a;
    asm("{ .reg .u64 t; cvta.to.shared.u64 t, %1; cvt.u32.u64 %0, t; }" : "=r"(a) : "l"(p));
    return a;
}
#define LDSM4(r, addr) \
    asm volatile("ldmatrix.sync.aligned.m8n8.x4.shared.b16 {%0,%1,%2,%3}, [%4];" \
        : "=r"((r)[0]), "=r"((r)[1]), "=r"((r)[2]), "=r"((r)[3]) : "r"(addr))

__device__ __forceinline__ void mma_bf16(float* c, const uint32_t* a, const uint32_t* b) {
    asm volatile("mma.sync.aligned.m16n8k16.row.col.f32.bf16.bf16.f32 "
        "{%0,%1,%2,%3}, {%4,%5,%6,%7}, {%8,%9}, {%0,%1,%2,%3};"
        : "+f"(c[0]), "+f"(c[1]), "+f"(c[2]), "+f"(c[3])
        : "r"(a[0]), "r"(a[1]), "r"(a[2]), "r"(a[3]), "r"(b[0]), "r"(b[1]));
}
#define CP_ASYNC16(sa, gp) \
    asm volatile("cp.async.cg.shared.global [%0], [%1], 16;" :: "r"(sa), "l"(gp))
#define CP_COMMIT() asm volatile("cp.async.commit_group;" ::: "memory")
#define CP_WAIT1()  asm volatile("cp.async.wait_group 1;" ::: "memory")
#define CP_WAIT0()  asm volatile("cp.async.wait_group 0;" ::: "memory")

// ---------------- scratch ----------------
__device__ float    g_Q [BH * LL * DD];            // fp32 Q (qb_kernel input)
__device__ float    g_V [BH * LL * DD];            // fp32 V (PV path)
__device__ unsigned g_MB[NSTRUCT * BB * LL * (LL/32)];
__device__ __nv_bfloat16 g_hsH[BB*LL*HIDN], g_hsL[BB*LL*HIDN];
__device__ __nv_bfloat16 g_WH [3*HIDN*HIDN], g_WL [3*HIDN*HIDN];
// pre-split bf16 operands for attention MMA
__device__ __nv_bfloat16 g_QH [BH * LL * DD], g_QL [BH * LL * DD];
__device__ __nv_bfloat16 g_KH [BH * LL * DD], g_KL [BH * LL * DD];
__device__ __nv_bfloat16 g_QBH[NSTRUCT * BH * LL * DD], g_QBL[NSTRUCT * BH * LL * DD];

// =============================================================================
// Kernel 0a: pack structure mask to bits.
// =============================================================================
__global__ void __launch_bounds__(256) pack_mask(const float* __restrict__ smask)
{
    size_t e = (size_t)blockIdx.x * 256 + threadIdx.x;
    float v = smask[e];
    unsigned bal = __ballot_sync(0xffffffffu, v != 0.f);
    if ((threadIdx.x & 31) == 0) g_MB[e >> 5] = bal;
}

// =============================================================================
// Kernel 0b/0c: split fp32 -> bf16 hi/lo
// =============================================================================
__device__ __forceinline__ void split2(float a, float b, __nv_bfloat162* H, __nv_bfloat162* L) {
    __nv_bfloat16 ah = __float2bfloat16_rn(a), bh = __float2bfloat16_rn(b);
    __nv_bfloat16 al = __float2bfloat16_rn(a - __bfloat162float(ah));
    __nv_bfloat16 bl = __float2bfloat16_rn(b - __bfloat162float(bh));
    *H = __nv_bfloat162(ah, bh);
    *L = __nv_bfloat162(al, bl);
}
__global__ void __launch_bounds__(256) cvt_hs(const float* __restrict__ hs)
{
    size_t i = (size_t)blockIdx.x * 256 + threadIdx.x;
    float4 v = ((const float4*)hs)[i];
    __nv_bfloat162 h0, l0, h1, l1;
    split2(v.x, v.y, &h0, &l0);
    split2(v.z, v.w, &h1, &l1);
    ((__nv_bfloat162*)g_hsH)[2*i]   = h0;
    ((__nv_bfloat162*)g_hsH)[2*i+1] = h1;
    ((__nv_bfloat162*)g_hsL)[2*i]   = l0;
    ((__nv_bfloat162*)g_hsL)[2*i+1] = l1;
}
__global__ void __launch_bounds__(256) cvt_w(const float* __restrict__ Wq,
                                             const float* __restrict__ Wk,
                                             const float* __restrict__ Wv)
{
    size_t i = (size_t)blockIdx.x * 256 + threadIdx.x;
    const size_t per = (size_t)HIDN*HIDN/4;
    const float* src = (i < per) ? Wq : (i < 2*per) ? Wk : Wv;
    size_t loc = i % per;
    float4 v = ((const float4*)src)[loc];
    __nv_bfloat162 h0, l0, h1, l1;
    split2(v.x, v.y, &h0, &l0);
    split2(v.z, v.w, &h1, &l1);
    ((__nv_bfloat162*)g_WH)[2*i]   = h0;
    ((__nv_bfloat162*)g_WH)[2*i+1] = h1;
    ((__nv_bfloat162*)g_WL)[2*i]   = l0;
    ((__nv_bfloat162*)g_WL)[2*i+1] = l1;
}

// =============================================================================
// Kernel 1: QKV projection on mma.sync bf16 (split bf16x3).
// =============================================================================
#define QT_ROWB 80
#define QT_TILE (128 * QT_ROWB)
#define QT_STAGE (4 * QT_TILE)
#define QT_SMEM (2 * QT_STAGE)
#define NCHUNK (HIDN / 32)

__global__ void __launch_bounds__(256) qkv_mma_kernel(
    const float* __restrict__ bq, const float* __restrict__ bk, const float* __restrict__ bv)
{
    extern __shared__ __align__(16) char smem[];
    const uint32_t sb = smem_u32(smem);

    const int t = threadIdx.x, wid = t >> 5, lane = t & 31;
    const int m0 = blockIdx.x * 128;
    const int n0 = blockIdx.y * 128;
    const int z  = blockIdx.z;
    const float* bias = (z == 0) ? bq : (z == 1) ? bk : bv;
    const __nv_bfloat16* BHg = g_WH + (size_t)z * HIDN * HIDN;
    const __nv_bfloat16* BLg = g_WL + (size_t)z * HIDN * HIDN;

    const int wm = (wid & 1) * 64;
    const int wn = (wid >> 1) * 32;

    float C[4][4][4];
#pragma unroll
    for (int i = 0; i < 4; i++)
#pragma unroll
        for (int j = 0; j < 4; j++)
#pragma unroll
            for (int k = 0; k < 4; k++) C[i][j][k] = 0.f;

    const uint32_t a_off = (uint32_t)((wm + (lane & 7) + ((lane >> 3) & 1) * 8) * QT_ROWB
                                      + ((lane >> 4) * 8) * 2);
    const uint32_t b_off = (uint32_t)((wn + (lane & 7) + (lane >> 4) * 8) * QT_ROWB
                                      + (((lane >> 3) & 1) * 8) * 2);

    const int lr0 = t >> 2, lu0 = t & 3;
    const int lr1 = (t + 256) >> 2, lu1 = t & 3;

    {
        const int k0 = 0;
        uint32_t s0 = sb;
#pragma unroll
        for (int p = 0; p < 2; ++p) {
            int r = p ? lr1 : lr0, u = p ? lu1 : lu0;
            uint32_t so = (uint32_t)(r * QT_ROWB + u * 16);
            size_t ga = (size_t)(m0 + r) * HIDN + k0 + u * 8;
            size_t gb = (size_t)(n0 + r) * HIDN + k0 + u * 8;
            CP_ASYNC16(s0 + 0*QT_TILE + so, g_hsH + ga);
            CP_ASYNC16(s0 + 1*QT_TILE + so, g_hsL + ga);
            CP_ASYNC16(s0 + 2*QT_TILE + so, BHg + gb);
            CP_ASYNC16(s0 + 3*QT_TILE + so, BLg + gb);
        }
        CP_COMMIT();
    }

    for (int ch = 0; ch < NCHUNK; ++ch) {
        if (ch + 1 < NCHUNK) {
            const int k0 = (ch + 1) * 32;
            uint32_t s1 = sb + ((ch + 1) & 1) * QT_STAGE;
#pragma unroll
            for (int p = 0; p < 2; ++p) {
                int r = p ? lr1 : lr0, u = p ? lu1 : lu0;
                uint32_t so = (uint32_t)(r * QT_ROWB + u * 16);
                size_t ga = (size_t)(m0 + r) * HIDN + k0 + u * 8;
                size_t gb = (size_t)(n0 + r) * HIDN + k0 + u * 8;
                CP_ASYNC16(s1 + 0*QT_TILE + so, g_hsH + ga);
                CP_ASYNC16(s1 + 1*QT_TILE + so, g_hsL + ga);
                CP_ASYNC16(s1 + 2*QT_TILE + so, BHg + gb);
                CP_ASYNC16(s1 + 3*QT_TILE + so, BLg + gb);
            }
            CP_COMMIT();
            CP_WAIT1();
        } else {
            CP_WAIT0();
        }
        __syncthreads();

        const uint32_t st = sb + (ch & 1) * QT_STAGE;
        const uint32_t aH = st + 0*QT_TILE + a_off;
        const uint32_t aL = st + 1*QT_TILE + a_off;
        const uint32_t bHb = st + 2*QT_TILE + b_off;
        const uint32_t bLb = st + 3*QT_TILE + b_off;

#pragma unroll
        for (int ks = 0; ks < 2; ++ks) {
            const uint32_t ko = ks * 32;
            uint32_t ah[4][4], al[4][4], bh[4][2], bl[4][2];
#pragma unroll
            for (int mt = 0; mt < 4; ++mt) {
                LDSM4(ah[mt], aH + mt * 16 * QT_ROWB + ko);
                LDSM4(al[mt], aL + mt * 16 * QT_ROWB + ko);
            }
#pragma unroll
            for (int p = 0; p < 2; ++p) {
                uint32_t r4[4];
                LDSM4(r4, bHb + p * 16 * QT_ROWB + ko);
                bh[2*p][0] = r4[0]; bh[2*p][1] = r4[1];
                bh[2*p+1][0] = r4[2]; bh[2*p+1][1] = r4[3];
                LDSM4(r4, bLb + p * 16 * QT_ROWB + ko);
                bl[2*p][0] = r4[0]; bl[2*p][1] = r4[1];
                bl[2*p+1][0] = r4[2]; bl[2*p+1][1] = r4[3];
            }
#pragma unroll
            for (int mt = 0; mt < 4; ++mt)
#pragma unroll
                for (int nt = 0; nt < 4; ++nt) {
                    mma_bf16(C[mt][nt], ah[mt], bh[nt]);
                    mma_bf16(C[mt][nt], ah[mt], bl[nt]);
                    mma_bf16(C[mt][nt], al[mt], bh[nt]);
                }
        }
        __syncthreads();
    }

    // ---- epilogue ----
#pragma unroll
    for (int mt = 0; mt < 4; ++mt) {
        const int m = m0 + wm + mt * 16 + (lane >> 2);
        const int b = m >> 9, l = m & 511;
#pragma unroll
        for (int nt = 0; nt < 4; ++nt) {
            const int n = n0 + wn + nt * 8 + (lane & 3) * 2;
            const int hd = n >> 6, d = n & 63;
            const float b0 = __ldg(bias + n), b1 = __ldg(bias + n + 1);
            const size_t o1 = ((size_t)(b * HH + hd) * LL + l) * DD + d;
            const size_t o2 = ((size_t)(b * HH + hd) * LL + (l + 8)) * DD + d;
            float v00 = C[mt][nt][0] + b0, v01 = C[mt][nt][1] + b1;
            float v10 = C[mt][nt][2] + b0, v11 = C[mt][nt][3] + b1;
            if (z == 0) {
                *(float2*)(g_Q + o1) = make_float2(v00, v01);
                *(float2*)(g_Q + o2) = make_float2(v10, v11);
                __nv_bfloat162 hh, llo;
                split2(v00, v01, &hh, &llo);
                *(__nv_bfloat162*)(g_QH + o1) = hh;
                *(__nv_bfloat162*)(g_QL + o1) = llo;
                split2(v10, v11, &hh, &llo);
                *(__nv_bfloat162*)(g_QH + o2) = hh;
                *(__nv_bfloat162*)(g_QL + o2) = llo;
            } else if (z == 1) {
                __nv_bfloat162 hh, llo;
                split2(v00, v01, &hh, &llo);
                *(__nv_bfloat162*)(g_KH + o1) = hh;
                *(__nv_bfloat162*)(g_KL + o1) = llo;
                split2(v10, v11, &hh, &llo);
                *(__nv_bfloat162*)(g_KH + o2) = hh;
                *(__nv_bfloat162*)(g_KL + o2) = llo;
            } else {
                *(float2*)(g_V + o1) = make_float2(v00, v01);
                *(float2*)(g_V + o2) = make_float2(v10, v11);
            }
        }
    }
}

// =============================================================================
// Kernel 2: QB = Q @ bili (SIMT), writes pre-split bf16 (coalesced 8B stores).
// =============================================================================
__global__ void __launch_bounds__(256) qb_kernel(const float* __restrict__ bili)
{
    const int mt = blockIdx.x, h = blockIdx.y, s = blockIdx.z;
    const int m0 = mt * 64;
    const int b = m0 >> 9, l0 = m0 & 511;
    const float* qbase = g_Q + (size_t)(b*HH + h) * LL * DD;
    const float* Bm    = bili + (size_t)(s*HH + h) * DD * DD;
    const size_t dstoff = (size_t)((s*BB + b)*HH + h) * LL * DD;

    __shared__ __align__(16) float As[16 * 68];
    __shared__ __align__(16) float Bs[16 * 68];

    const int t = threadIdx.x;
    const int mload = t >> 2, kv = t & 3;
    const int kl = t >> 4, nv = t & 15;
    const int ty = t >> 4, tx = t & 15;

    float c[4][4];
#pragma unroll
    for (int i = 0; i < 4; i++)
#pragma unroll
        for (int j = 0; j < 4; j++) c[i][j] = 0.f;

    for (int k0 = 0; k0 < DD; k0 += 16) {
        float4 a4 = *(const float4*)(qbase + (size_t)(l0 + mload) * DD + k0 + kv * 4);
        As[(kv*4+0)*68 + mload] = a4.x;
        As[(kv*4+1)*68 + mload] = a4.y;
        As[(kv*4+2)*68 + mload] = a4.z;
        As[(kv*4+3)*68 + mload] = a4.w;
        float4 b4 = *(const float4*)(Bm + (size_t)(k0 + kl) * DD + nv * 4);
        Bs[kl*68 + nv*4+0] = b4.x;
        Bs[kl*68 + nv*4+1] = b4.y;
        Bs[kl*68 + nv*4+2] = b4.z;
        Bs[kl*68 + nv*4+3] = b4.w;
        __syncthreads();
#pragma unroll
        for (int k = 0; k < 16; k++) {
            float4 av4 = *(const float4*)&As[k*68 + ty*4];
            float4 bv4 = *(const float4*)&Bs[k*68 + tx*4];
            float a[4] = {av4.x, av4.y, av4.z, av4.w};
            float bb[4] = {bv4.x, bv4.y, bv4.z, bv4.w};
#pragma unroll
            for (int i = 0; i < 4; i++)
#pragma unroll
                for (int j = 0; j < 4; j++) c[i][j] += a[i] * bb[j];
        }
        __syncthreads();
    }

#pragma unroll
    for (int i = 0; i < 4; i++) {
        const size_t ro = dstoff + (size_t)(l0 + ty*4 + i) * DD + tx*4;
        __nv_bfloat162 h0, l0b, h1, l1b;
        split2(c[i][0], c[i][1], &h0, &l0b);
        split2(c[i][2], c[i][3], &h1, &l1b);
        uint2 hv, lv;
        hv.x = *(uint32_t*)&h0; hv.y = *(uint32_t*)&h1;
        lv.x = *(uint32_t*)&l0b; lv.y = *(uint32_t*)&l1b;
        *(uint2*)(g_QBH + ro) = hv;
        *(uint2*)(g_QBL + ro) = lv;
    }
}

// =============================================================================
// Kernel 3: fused attention, 32 q-rows/block, 64-wide j-tiles, 99.3KB smem
// -> 2 blocks/SM (16 warps). Warp (w&1, w>>1) owns a 16m x 16n S fragment.
// =============================================================================
#define A_QH 0
#define A_QL (A_QH + 6*32*144)          // 27648
#define A_KH (A_QL + 6*32*144)          // 55296
#define A_KL (A_KH + 64*144)            // 64512
#define A_VT (A_KL + 64*144)            // 73728
#define A_SC (A_VT + 64*66*4)           // 90624
#define A_TOT (A_SC + 32*68*4)          // 99328

__device__ __forceinline__ float warp_max(float v) {
#pragma unroll
    for (int off = 16; off > 0; off >>= 1)
        v = fmaxf(v, __shfl_xor_sync(0xffffffffu, v, off));
    return v;
}
__device__ __forceinline__ float warp_sum(float v) {
#pragma unroll
    for (int off = 16; off > 0; off >>= 1)
        v += __shfl_xor_sync(0xffffffffu, v, off);
    return v;
}

__global__ void __launch_bounds__(256) attn_kernel(
    const float* __restrict__ amask,
    const float* __restrict__ absb,
    float* __restrict__ out)
{
    extern __shared__ __align__(16) char smem[];
    const uint32_t sb = smem_u32(smem);
    float* vt = (float*)(smem + A_VT);
    float* sc = (float*)(smem + A_SC);

    const int t    = threadIdx.x;
    const int w    = t >> 5;
    const int lane = t & 31;
    const int bh   = blockIdx.y;
    const int b = bh / HH, h = bh % HH;
    const int i0 = blockIdx.x * 32;

    const __nv_bfloat16* QHb = g_QH + (size_t)bh * LL * DD;
    const __nv_bfloat16* QLb = g_QL + (size_t)bh * LL * DD;
    const __nv_bfloat16* KHb = g_KH + (size_t)bh * LL * DD;
    const __nv_bfloat16* KLb = g_KL + (size_t)bh * LL * DD;
    const float* Vb = g_V + (size_t)bh * LL * DD;

    // ---- load q + 5 qb components (pre-split bf16, straight copies) ----
    for (int f = t; f < 6 * 32 * 8; f += 256) {
        int c = f >> 8;             // 32 rows * 8 u4 = 256 per component
        int r = (f >> 3) & 31;
        int u = f & 7;
        const size_t go = (c == 0)
            ? (size_t)bh * LL * DD + (size_t)(i0 + r) * DD + u * 8
            : (size_t)((c - 1) * BB + b) * HH * LL * DD + (size_t)h * LL * DD
              + (size_t)(i0 + r) * DD + u * 8;
        const __nv_bfloat16* sH = (c == 0) ? (g_QH + go) : (g_QBH + go);
        const __nv_bfloat16* sL = (c == 0) ? (g_QL + go) : (g_QBL + go);
        char* p = smem + (c * 32 + r) * 144 + u * 16;
        *(uint4*)(p + A_QH) = *(const uint4*)sH;
        *(uint4*)(p + A_QL) = *(const uint4*)sL;
    }

    float ab[NSTRUCT];
#pragma unroll
    for (int s = 0; s < NSTRUCT; ++s) ab[s] = __ldg(absb + s*HH + h);

    float mrow[4], lrow[4];
    ull ctx2[4][2];
#pragma unroll
    for (int i = 0; i < 4; ++i) {
        mrow[i] = -1e30f; lrow[i] = 0.f;
        ctx2[i][0] = 0ULL; ctx2[i][1] = 0ULL;
    }

    const int row0 = w * 4;              // softmax/PV row ownership (4 rows)
    const int wm = (w & 1) * 16;         // mma m offset
    const int wn = (w >> 1) * 16;        // mma n offset

    const uint32_t a_base = sb + A_QH
        + (uint32_t)((wm + (lane & 7) + ((lane >> 3) & 1) * 8) * 144 + (lane >> 4) * 16);
    const uint32_t b_base = sb + A_KH
        + (uint32_t)((wn + (lane & 7) + (lane >> 4) * 8) * 144 + ((lane >> 3) & 1) * 16);
    const uint32_t QLOFF = A_QL - A_QH;
    const uint32_t KLOFF = A_KL - A_KH;

    const int widx_base = (wn >> 5);     // 0 for wn<32, 1 otherwise
    const int bp0 = (wn & 31) + (lane & 3) * 2;

    for (int jt = 0; jt < 8; ++jt) {
        const int j0 = jt * 64;
        __syncthreads();
        // ---- load K tile (pre-split bf16) ----
        for (int f = t; f < 64 * 8; f += 256) {
            int j = f >> 3, u = f & 7;
            const size_t go = (size_t)(j0 + j) * DD + u * 8;
            char* p = smem + j * 144 + u * 16;
            *(uint4*)(p + A_KH) = *(const uint4*)(KHb + go);
            *(uint4*)(p + A_KL) = *(const uint4*)(KLb + go);
        }
        // ---- load V tile (fp32, transposed [d][j]) ----
        for (int f = t; f < 1024; f += 256) {
            int j = f >> 4, dv = f & 15;
            float4 v4 = *(const float4*)(Vb + (size_t)(j0 + j) * DD + dv * 4);
            vt[(dv*4+0)*66 + j] = v4.x;
            vt[(dv*4+1)*66 + j] = v4.y;
            vt[(dv*4+2)*66 + j] = v4.z;
            vt[(dv*4+3)*66 + j] = v4.w;
        }
        __syncthreads();

        // ---- MMA: S fragment [2 nt][4] ----
        float S[2][4];
#pragma unroll
        for (int j = 0; j < 2; ++j)
#pragma unroll
            for (int k = 0; k < 4; ++k) S[j][k] = 0.f;

        for (int c = 0; c < 6; ++c) {
            float Sc[2][4];
            float (*acc)[4] = (c == 0) ? S : Sc;
            if (c != 0) {
#pragma unroll
                for (int j = 0; j < 2; ++j)
#pragma unroll
                    for (int k = 0; k < 4; ++k) Sc[j][k] = 0.f;
            }
            const uint32_t aH = a_base + (uint32_t)(c * 32 * 144);
#pragma unroll
            for (int ks = 0; ks < 4; ++ks) {
                const uint32_t ko = ks * 32;
                uint32_t ah[4], al[4], bhf[2][2], blf[2][2];
                LDSM4(ah, aH + ko);
                LDSM4(al, aH + QLOFF + ko);
                {
                    uint32_t r4[4];
                    LDSM4(r4, b_base + ko);
                    bhf[0][0] = r4[0]; bhf[0][1] = r4[1];
                    bhf[1][0] = r4[2]; bhf[1][1] = r4[3];
                    LDSM4(r4, b_base + KLOFF + ko);
                    blf[0][0] = r4[0]; blf[0][1] = r4[1];
                    blf[1][0] = r4[2]; blf[1][1] = r4[3];
                }
#pragma unroll
                for (int nt = 0; nt < 2; ++nt) {
                    mma_bf16(acc[nt], ah, bhf[nt]);
                    mma_bf16(acc[nt], ah, blf[nt]);
                    mma_bf16(acc[nt], al, bhf[nt]);
                }
            }
            if (c != 0) {
                const int s = c - 1;
                const float abs_s = ab[s];
                const size_t mrowbase = ((size_t)(s*BB + b) * LL + i0 + wm) * 16;
                const int rloc = lane >> 2;
                const size_t wi = (size_t)(jt * 2 + widx_base);
                unsigned mw0 = g_MB[mrowbase + (size_t)rloc * 16 + wi];
                unsigned mw1 = g_MB[mrowbase + (size_t)(rloc + 8) * 16 + wi];
#pragma unroll
                for (int nt = 0; nt < 2; ++nt) {
                    const int bp = bp0 + nt * 8;
                    S[nt][0] += (float)((mw0 >> bp) & 1u)     * (Sc[nt][0] + abs_s);
                    S[nt][1] += (float)((mw0 >> (bp+1)) & 1u) * (Sc[nt][1] + abs_s);
                    S[nt][2] += (float)((mw1 >> bp) & 1u)     * (Sc[nt][2] + abs_s);
                    S[nt][3] += (float)((mw1 >> (bp+1)) & 1u) * (Sc[nt][3] + abs_s);
                }
            }
        }

        // ---- spill S fragments to sc ----
        {
            const int rr = wm + (lane >> 2);
#pragma unroll
            for (int nt = 0; nt < 2; ++nt) {
                const int cc = wn + nt * 8 + (lane & 3) * 2;
                *(float2*)&sc[rr * 68 + cc]       = make_float2(S[nt][0], S[nt][1]);
                *(float2*)&sc[(rr + 8) * 68 + cc] = make_float2(S[nt][2], S[nt][3]);
            }
        }
        __syncthreads();

        // ---- online softmax (warp owns rows row0..row0+3) ----
        float amv[2];
        amv[0] = __ldg(amask + (size_t)b * LL + j0 + lane);
        amv[1] = __ldg(amask + (size_t)b * LL + j0 + lane + 32);

#pragma unroll
        for (int ii = 0; ii < 4; ++ii) {
            const int r = row0 + ii;
            float lg0 = sc[r * 68 + lane]      * 0.125f + amv[0];
            float lg1 = sc[r * 68 + lane + 32] * 0.125f + amv[1];
            float mt = warp_max(fmaxf(lg0, lg1));
            float mnew = fmaxf(mrow[ii], mt);
            float corr = __expf(mrow[ii] - mnew);
            mrow[ii] = mnew;
            float p0 = __expf(lg0 - mnew);
            float p1 = __expf(lg1 - mnew);
            sc[r * 68 + lane]      = p0;
            sc[r * 68 + lane + 32] = p1;
            float psum = warp_sum(p0 + p1);
            lrow[ii] = lrow[ii] * corr + psum;
            ull c2 = pack2(corr, corr);
            mul2(ctx2[ii][0], c2);
            mul2(ctx2[ii][1], c2);
        }
        __syncwarp();

        // ---- PV (FFMA2): vt [d][j=64] ----
        const float* vr0 = &vt[lane * 66];
        const float* vr1 = &vt[(lane + 32) * 66];
#pragma unroll 4
        for (int j2 = 0; j2 < 32; ++j2) {
            ull vv0 = *(const ull*)(vr0 + 2*j2);
            ull vv1 = *(const ull*)(vr1 + 2*j2);
#pragma unroll
            for (int ii = 0; ii < 4; ++ii) {
                ull pp = *(const ull*)&sc[(row0 + ii) * 68 + 2*j2];
                fma2(ctx2[ii][0], pp, vv0);
                fma2(ctx2[ii][1], pp, vv1);
            }
        }
    }

    // ---- finalize ----
#pragma unroll
    for (int ii = 0; ii < 4; ++ii) {
        const int ig = i0 + row0 + ii;
        float inv = 1.f / lrow[ii];
        float* op = out + (size_t)(b * LL + ig) * (HH*DD) + h * DD;
        float2 c0 = unpack2(ctx2[ii][0]);
        float2 c1 = unpack2(ctx2[ii][1]);
        op[lane]      = (c0.x + c0.y) * inv;
        op[lane + 32] = (c1.x + c1.y) * inv;
    }
}

// =============================================================================
extern "C" void kernel_launch(void* const* d_in, const int* in_sizes, int n_in,
                              void* d_out, int out_size)
{
    const float* hs   = (const float*)d_in[0];
    const float* am   = (const float*)d_in[1];
    const float* smk  = (const float*)d_in[2];
    const float* Wq   = (const float*)d_in[3];
    const float* bq   = (const float*)d_in[4];
    const float* Wk   = (const float*)d_in[5];
    const float* bk   = (const float*)d_in[6];
    const float* Wv   = (const float*)d_in[7];
    const float* bv   = (const float*)d_in[8];
    const float* bili = (const float*)d_in[9];
    const float* absb = (const float*)d_in[10];
    float* out = (float*)d_out;

    pack_mask<<<(NSTRUCT*BB*LL*LL)/256, 256>>>(smk);
    cvt_hs<<<(BB*LL*HIDN/4)/256, 256>>>(hs);
    cvt_w<<<(3*HIDN*HIDN/4)/256, 256>>>(Wq, Wk, Wv);

    cudaFuncSetAttribute(qkv_mma_kernel, cudaFuncAttributeMaxDynamicSharedMemorySize, QT_SMEM);
    qkv_mma_kernel<<<dim3(64, 6, 3), 256, QT_SMEM>>>(bq, bk, bv);

    qb_kernel<<<dim3(128, 12, 5), 256>>>(bili);

    cudaFuncSetAttribute(attn_kernel, cudaFuncAttributeMaxDynamicSharedMemorySize, A_TOT);
    attn_kernel<<<dim3(16, 192), 256, A_TOT>>>(am, absb, out);
}